// round 3
// baseline (speedup 1.0000x reference)
#include <cuda_runtime.h>
#include <cuda_bf16.h>
#include <mma.h>
#include <math.h>
#include <cstdint>

using namespace nvcuda;

#define NN 30000
#define NNP 30080     // padded to multiple of 128
#define EE 300000
#define EEP 300032
#define HH 8
#define HID 256

// ===================== scratch (device globals) =============================
__device__ float g_q[NN * HID];
__device__ float g_k[NN * HID];
__device__ float g_v[NN * HID];
__device__ float g_skip[NN * HID];
__device__ float g_e[EE * HID];
__device__ float g_logits[EE * HH];
__device__ float g_m[NN * HH];
__device__ float g_denom[NN * HH];
__device__ float g_num[NN * HID];
__device__ float g_out[NN * HID];

// bf16 hi/lo operands (padded row counts; pad rows stay zero)
__device__ __nv_bfloat16 g_xh[NNP * HID],   g_xl[NNP * HID];
__device__ __nv_bfloat16 g_outh[NNP * HID], g_outl[NNP * HID];
__device__ __nv_bfloat16 g_h1h[NNP * HID],  g_h1l[NNP * HID];
__device__ __nv_bfloat16 g_eah[EEP * 32],   g_eal[EEP * 32];
// weights kept [K,256] row-major as bf16 hi/lo (no transpose needed for wmma B)
__device__ __nv_bfloat16 g_wq_h[256 * 256], g_wq_l[256 * 256];
__device__ __nv_bfloat16 g_wk_h[256 * 256], g_wk_l[256 * 256];
__device__ __nv_bfloat16 g_wv_h[256 * 256], g_wv_l[256 * 256];
__device__ __nv_bfloat16 g_ws_h[256 * 256], g_ws_l[256 * 256];
__device__ __nv_bfloat16 g_w1_h[256 * 256], g_w1_l[256 * 256];
__device__ __nv_bfloat16 g_w2_h[256 * 256], g_w2_l[256 * 256];
__device__ __nv_bfloat16 g_we_h[32 * 256],  g_we_l[32 * 256];

// ===================== helpers ==============================================
__device__ __forceinline__ float gelu_tanh(float x) {
    float x3 = x * x * x;
    float t = tanhf(0.7978845608028654f * (x + 0.044715f * x3));
    return 0.5f * x * (1.0f + t);
}
__device__ __forceinline__ void atomicMaxF(float* addr, float val) {
    if (val >= 0.0f) atomicMax(reinterpret_cast<int*>(addr), __float_as_int(val));
    else             atomicMin(reinterpret_cast<unsigned int*>(addr), __float_as_uint(val));
}
__device__ __forceinline__ void split2(float v, __nv_bfloat16& h, __nv_bfloat16& l) {
    h = __float2bfloat16(v);
    l = __float2bfloat16(v - __bfloat162float(h));
}
__device__ __forceinline__ void redAdd4(float* p, float a, float b, float c, float d) {
    asm volatile("red.global.add.v4.f32 [%0], {%1, %2, %3, %4};"
                 :: "l"(p), "f"(a), "f"(b), "f"(c), "f"(d) : "memory");
}

// ===================== conversion kernels ===================================
__global__ void cvt_split(const float* __restrict__ src, __nv_bfloat16* __restrict__ h,
                          __nv_bfloat16* __restrict__ l, int n) {
    int i = blockIdx.x * blockDim.x + threadIdx.x;
    if (i >= n) return;
    split2(src[i], h[i], l[i]);
}

// ===================== wmma GEMM ============================================
// C[M,256] = (Ah+Al)[M,KF] @ (Bh+Bl)[KF,256]   (3-term bf16 split, fp32 acc)
// CTA: 128 rows x 64 cols, 8 warps (4m x 2n), warp tile 32x32.
// EPI: 0 plain f32 | 1 +bias f32 | 2 +bias,gelu -> bf16 hi/lo | 3 +bias,gelu,+res -> f32
template <int KF, int EPI>
__global__ void __launch_bounds__(256) wgemm(
    const __nv_bfloat16* __restrict__ Ah, const __nv_bfloat16* __restrict__ Al,
    const __nv_bfloat16* __restrict__ Bh, const __nv_bfloat16* __restrict__ Bl,
    const float* __restrict__ bias, const float* __restrict__ res,
    float* __restrict__ Cf, __nv_bfloat16* __restrict__ Ch, __nv_bfloat16* __restrict__ Cl,
    int M)
{
    extern __shared__ char smem[];
    __nv_bfloat16* Bsh = reinterpret_cast<__nv_bfloat16*>(smem);         // [KF][64]
    __nv_bfloat16* Bsl = Bsh + KF * 64;
    float* stage = reinterpret_cast<float*>(smem);                       // reused post-mainloop

    int tid = threadIdx.x;
    int wid = tid >> 5;
    int lane = tid & 31;
    int row0 = blockIdx.x * 128;
    int n0 = blockIdx.y * 64;
    int mw = wid >> 1;        // 0..3
    int nw = wid & 1;         // 0..1

    // stage B tiles into smem (uint = 2 bf16, coalesced)
    for (int i = tid; i < KF * 32; i += 256) {
        int k = i >> 5;
        int j = (i & 31);
        reinterpret_cast<uint32_t*>(Bsh)[k * 32 + j] =
            *reinterpret_cast<const uint32_t*>(Bh + (size_t)k * 256 + n0 + 2 * j);
        reinterpret_cast<uint32_t*>(Bsl)[k * 32 + j] =
            *reinterpret_cast<const uint32_t*>(Bl + (size_t)k * 256 + n0 + 2 * j);
    }
    __syncthreads();

    wmma::fragment<wmma::accumulator, 16, 16, 16, float> acc[2][2];
#pragma unroll
    for (int i = 0; i < 2; i++)
#pragma unroll
        for (int j = 0; j < 2; j++) wmma::fill_fragment(acc[i][j], 0.0f);

    const __nv_bfloat16* Abh = Ah + (size_t)(row0 + mw * 32) * KF;
    const __nv_bfloat16* Abl = Al + (size_t)(row0 + mw * 32) * KF;

#pragma unroll
    for (int k = 0; k < KF; k += 16) {
        wmma::fragment<wmma::matrix_a, 16, 16, 16, __nv_bfloat16, wmma::row_major> ah[2], al[2];
        wmma::fragment<wmma::matrix_b, 16, 16, 16, __nv_bfloat16, wmma::row_major> bh[2], bl[2];
        wmma::load_matrix_sync(ah[0], Abh + k, KF);
        wmma::load_matrix_sync(ah[1], Abh + (size_t)16 * KF + k, KF);
        wmma::load_matrix_sync(al[0], Abl + k, KF);
        wmma::load_matrix_sync(al[1], Abl + (size_t)16 * KF + k, KF);
        wmma::load_matrix_sync(bh[0], Bsh + k * 64 + nw * 32, 64);
        wmma::load_matrix_sync(bh[1], Bsh + k * 64 + nw * 32 + 16, 64);
        wmma::load_matrix_sync(bl[0], Bsl + k * 64 + nw * 32, 64);
        wmma::load_matrix_sync(bl[1], Bsl + k * 64 + nw * 32 + 16, 64);
#pragma unroll
        for (int i = 0; i < 2; i++)
#pragma unroll
            for (int j = 0; j < 2; j++) {
                wmma::mma_sync(acc[i][j], ah[i], bh[j], acc[i][j]);
                wmma::mma_sync(acc[i][j], ah[i], bl[j], acc[i][j]);
                wmma::mma_sync(acc[i][j], al[i], bh[j], acc[i][j]);
            }
    }
    __syncthreads();  // all warps done reading B before overwriting smem with stage

    float* st = stage + wid * 32 * 32;
#pragma unroll
    for (int i = 0; i < 2; i++)
#pragma unroll
        for (int j = 0; j < 2; j++)
            wmma::store_matrix_sync(st + i * 16 * 32 + j * 16, acc[i][j], 32, wmma::mem_row_major);
    __syncwarp();

    float bval = (EPI >= 1) ? bias[n0 + nw * 32 + lane] : 0.0f;
#pragma unroll 4
    for (int r = 0; r < 32; r++) {
        int grow = row0 + mw * 32 + r;
        if (grow >= M) break;
        float v = st[r * 32 + lane];
        if (EPI >= 1) v += bval;
        if (EPI >= 2) v = gelu_tanh(v);
        size_t idx = (size_t)grow * 256 + n0 + nw * 32 + lane;
        if (EPI == 2) {
            __nv_bfloat16 h, l;
            split2(v, h, l);
            Ch[idx] = h;
            Cl[idx] = l;
        } else {
            if (EPI == 3) v += res[idx];
            Cf[idx] = v;
        }
    }
}

// ===================== attention kernels ====================================
__global__ void init_kernel() {
    int i = blockIdx.x * blockDim.x + threadIdx.x;
    if (i < NN * HH) { g_m[i] = -INFINITY; g_denom[i] = 0.0f; }
    if (i < NN * HID) g_num[i] = 0.0f;
}

__global__ void edge_logits_kernel(const int* __restrict__ ei) {
    int warp = (blockIdx.x * blockDim.x + threadIdx.x) >> 5;
    int lane = threadIdx.x & 31;
    if (warp >= EE) return;
    int src = ei[warp];
    int dst = ei[EE + warp];
    const float* qrow = g_q + (size_t)dst * 256;
    const float* krow = g_k + (size_t)src * 256;
    const float* erow = g_e + (size_t)warp * 256;
    float s[8];
#pragma unroll
    for (int h = 0; h < 8; h++) {
        int j = h * 32 + lane;
        s[h] = qrow[j] * (krow[j] + erow[j]);
    }
#pragma unroll
    for (int off = 16; off; off >>= 1)
#pragma unroll
        for (int h = 0; h < 8; h++) s[h] += __shfl_xor_sync(0xffffffffu, s[h], off);
    if (lane < 8) {
        float lg = s[lane] * 0.17677669529663687f;
        g_logits[(size_t)warp * 8 + lane] = lg;
        atomicMaxF(&g_m[dst * 8 + lane], lg);
    }
}

__global__ void edge_accum_kernel(const int* __restrict__ ei) {
    int warp = (blockIdx.x * blockDim.x + threadIdx.x) >> 5;
    int lane = threadIdx.x & 31;
    if (warp >= EE) return;
    int src = ei[warp];
    int dst = ei[EE + warp];
    float a = 0.0f;
    if (lane < 8) {
        a = expf(g_logits[(size_t)warp * 8 + lane] - g_m[dst * 8 + lane]);
        atomicAdd(&g_denom[dst * 8 + lane], a);
    }
    float ah[8];
#pragma unroll
    for (int h = 0; h < 8; h++) ah[h] = __shfl_sync(0xffffffffu, a, h);

    const float4* v4 = reinterpret_cast<const float4*>(g_v + (size_t)src * 256);
    const float4* e4 = reinterpret_cast<const float4*>(g_e + (size_t)warp * 256);
    float* nrow = g_num + (size_t)dst * 256;
#pragma unroll
    for (int half = 0; half < 2; half++) {
        int col4 = half * 32 + lane;        // float4 index 0..63
        float al = ah[col4 >> 3];           // head = (col4*4)/32
        float4 vv = v4[col4];
        float4 ee = e4[col4];
        redAdd4(nrow + col4 * 4,
                (vv.x + ee.x) * al, (vv.y + ee.y) * al,
                (vv.z + ee.z) * al, (vv.w + ee.w) * al);
    }
}

__global__ void node_out_kernel() {
    int i = blockIdx.x * blockDim.x + threadIdx.x;
    if (i >= NN * HID) return;
    int n = i >> 8;
    int h = (i & 255) >> 5;
    float o = g_num[i] / (g_denom[n * 8 + h] + 1e-16f) + g_skip[i];
    g_out[i] = o;
    // padded bf16 arrays: row index identical (NN rows written, pad rows stay 0)
    split2(o, g_outh[i], g_outl[i]);
}

// ===================== launch ===============================================
extern "C" void kernel_launch(void* const* d_in, const int* in_sizes, int n_in,
                              void* d_out, int out_size) {
    const float* x         = (const float*)d_in[0];
    const int*   edge_idx  = (const int*)d_in[1];
    const float* edge_attr = (const float*)d_in[2];
    const float* Wq = (const float*)d_in[3];
    const float* bq = (const float*)d_in[4];
    const float* Wk = (const float*)d_in[5];
    const float* bk = (const float*)d_in[6];
    const float* Wv = (const float*)d_in[7];
    const float* bv = (const float*)d_in[8];
    const float* We = (const float*)d_in[9];
    const float* Wskip = (const float*)d_in[10];
    const float* W1 = (const float*)d_in[11];
    const float* b1 = (const float*)d_in[12];
    const float* W2 = (const float*)d_in[13];
    const float* b2 = (const float*)d_in[14];

    void *pq, *pk, *pv, *pskip, *pe, *pout;
    void *pxh, *pxl, *pouth, *poutl, *ph1h, *ph1l, *peah, *peal;
    void *pwqh, *pwql, *pwkh, *pwkl, *pwvh, *pwvl, *pwsh, *pwsl;
    void *pw1h, *pw1l, *pw2h, *pw2l, *pweh, *pwel;
    cudaGetSymbolAddress(&pq, g_q);       cudaGetSymbolAddress(&pk, g_k);
    cudaGetSymbolAddress(&pv, g_v);       cudaGetSymbolAddress(&pskip, g_skip);
    cudaGetSymbolAddress(&pe, g_e);       cudaGetSymbolAddress(&pout, g_out);
    cudaGetSymbolAddress(&pxh, g_xh);     cudaGetSymbolAddress(&pxl, g_xl);
    cudaGetSymbolAddress(&pouth, g_outh); cudaGetSymbolAddress(&poutl, g_outl);
    cudaGetSymbolAddress(&ph1h, g_h1h);   cudaGetSymbolAddress(&ph1l, g_h1l);
    cudaGetSymbolAddress(&peah, g_eah);   cudaGetSymbolAddress(&peal, g_eal);
    cudaGetSymbolAddress(&pwqh, g_wq_h);  cudaGetSymbolAddress(&pwql, g_wq_l);
    cudaGetSymbolAddress(&pwkh, g_wk_h);  cudaGetSymbolAddress(&pwkl, g_wk_l);
    cudaGetSymbolAddress(&pwvh, g_wv_h);  cudaGetSymbolAddress(&pwvl, g_wv_l);
    cudaGetSymbolAddress(&pwsh, g_ws_h);  cudaGetSymbolAddress(&pwsl, g_ws_l);
    cudaGetSymbolAddress(&pw1h, g_w1_h);  cudaGetSymbolAddress(&pw1l, g_w1_l);
    cudaGetSymbolAddress(&pw2h, g_w2_h);  cudaGetSymbolAddress(&pw2l, g_w2_l);
    cudaGetSymbolAddress(&pweh, g_we_h);  cudaGetSymbolAddress(&pwel, g_we_l);

    const int SMEM_NODE = 256 * 64 * 2 * 2;   // 65536 (stage 32KB fits inside)
    const int SMEM_EDGE = 32768;              // stage dominates (B tile is 8KB)
    cudaFuncSetAttribute(wgemm<256,0>, cudaFuncAttributeMaxDynamicSharedMemorySize, SMEM_NODE);
    cudaFuncSetAttribute(wgemm<256,1>, cudaFuncAttributeMaxDynamicSharedMemorySize, SMEM_NODE);
    cudaFuncSetAttribute(wgemm<256,2>, cudaFuncAttributeMaxDynamicSharedMemorySize, SMEM_NODE);
    cudaFuncSetAttribute(wgemm<256,3>, cudaFuncAttributeMaxDynamicSharedMemorySize, SMEM_NODE);
    cudaFuncSetAttribute(wgemm<32,0>,  cudaFuncAttributeMaxDynamicSharedMemorySize, SMEM_EDGE);

    typedef __nv_bfloat16 bf;

    init_kernel<<<(NN * HID + 255) / 256, 256>>>();

    // conversions (weights stay [K,256]; no transpose needed)
    cvt_split<<<(NN * HID + 255) / 256, 256>>>(x, (bf*)pxh, (bf*)pxl, NN * HID);
    cvt_split<<<(EE * 32 + 255) / 256, 256>>>(edge_attr, (bf*)peah, (bf*)peal, EE * 32);
    cvt_split<<<(256 * 256 + 255) / 256, 256>>>(Wq, (bf*)pwqh, (bf*)pwql, 256 * 256);
    cvt_split<<<(256 * 256 + 255) / 256, 256>>>(Wk, (bf*)pwkh, (bf*)pwkl, 256 * 256);
    cvt_split<<<(256 * 256 + 255) / 256, 256>>>(Wv, (bf*)pwvh, (bf*)pwvl, 256 * 256);
    cvt_split<<<(256 * 256 + 255) / 256, 256>>>(Wskip, (bf*)pwsh, (bf*)pwsl, 256 * 256);
    cvt_split<<<(256 * 256 + 255) / 256, 256>>>(W1, (bf*)pw1h, (bf*)pw1l, 256 * 256);
    cvt_split<<<(256 * 256 + 255) / 256, 256>>>(W2, (bf*)pw2h, (bf*)pw2l, 256 * 256);
    cvt_split<<<(32 * 256 + 255) / 256, 256>>>(We, (bf*)pweh, (bf*)pwel, 32 * 256);

    dim3 gN(NNP / 128, 4);
    dim3 gE(EEP / 128, 4);

    // projections
    wgemm<256,1><<<gN, 256, SMEM_NODE>>>((bf*)pxh, (bf*)pxl, (bf*)pwqh, (bf*)pwql,
                                         bq, nullptr, (float*)pq, nullptr, nullptr, NN);
    wgemm<256,1><<<gN, 256, SMEM_NODE>>>((bf*)pxh, (bf*)pxl, (bf*)pwkh, (bf*)pwkl,
                                         bk, nullptr, (float*)pk, nullptr, nullptr, NN);
    wgemm<256,1><<<gN, 256, SMEM_NODE>>>((bf*)pxh, (bf*)pxl, (bf*)pwvh, (bf*)pwvl,
                                         bv, nullptr, (float*)pv, nullptr, nullptr, NN);
    wgemm<256,0><<<gN, 256, SMEM_NODE>>>((bf*)pxh, (bf*)pxl, (bf*)pwsh, (bf*)pwsl,
                                         nullptr, nullptr, (float*)pskip, nullptr, nullptr, NN);
    // edge projection e = edge_attr @ We
    wgemm<32,0><<<gE, 256, SMEM_EDGE>>>((bf*)peah, (bf*)peal, (bf*)pweh, (bf*)pwel,
                                        nullptr, nullptr, (float*)pe, nullptr, nullptr, EE);

    // attention
    int edgeBlocks = (EE + 7) / 8;   // warp per edge, 8 warps/block
    edge_logits_kernel<<<edgeBlocks, 256>>>(edge_idx);
    edge_accum_kernel<<<edgeBlocks, 256>>>(edge_idx);
    node_out_kernel<<<(NN * HID + 255) / 256, 256>>>();

    // MLP
    wgemm<256,2><<<gN, 256, SMEM_NODE>>>((bf*)pouth, (bf*)poutl, (bf*)pw1h, (bf*)pw1l,
                                         b1, nullptr, nullptr, (bf*)ph1h, (bf*)ph1l, NN);
    wgemm<256,3><<<gN, 256, SMEM_NODE>>>((bf*)ph1h, (bf*)ph1l, (bf*)pw2h, (bf*)pw2l,
                                         b2, (const float*)pout, (float*)d_out, nullptr, nullptr, NN);
}

// round 4
// speedup vs baseline: 1.7283x; 1.7283x over previous
#include <cuda_runtime.h>
#include <cuda_bf16.h>
#include <mma.h>
#include <math.h>
#include <cstdint>

using namespace nvcuda;
typedef __nv_bfloat16 bf;

#define NN 30000
#define NNP 30080
#define EE 300000
#define EEP 300032
#define HH 8
#define HID 256

// ===================== PTX helpers ==========================================
__device__ __forceinline__ uint32_t smem_u32(const void* p) {
    uint32_t a;
    asm("{ .reg .u64 t; cvta.to.shared.u64 t, %1; cvt.u32.u64 %0, t; }" : "=r"(a) : "l"(p));
    return a;
}
#define CP_ASYNC16(saddr, gptr) \
    asm volatile("cp.async.cg.shared.global [%0], [%1], 16;" :: "r"(saddr), "l"(gptr))
#define CP_COMMIT() asm volatile("cp.async.commit_group;" ::: "memory")
#define CP_WAIT(n)  asm volatile("cp.async.wait_group %0;" :: "n"(n) : "memory")

__device__ __forceinline__ void redAdd4(float* p, float a, float b, float c, float d) {
    asm volatile("red.global.add.v4.f32 [%0], {%1, %2, %3, %4};"
                 :: "l"(p), "f"(a), "f"(b), "f"(c), "f"(d) : "memory");
}

// ===================== scratch ==============================================
__device__ float g_q[NN * HID];
__device__ float g_k[NN * HID];
__device__ float g_v[NN * HID];
__device__ float g_skip[NN * HID];
__device__ float g_e[EE * HID];
__device__ float g_logits[EE * HH];
__device__ float g_m[NN * HH];
__device__ float g_denom[NN * HH];
__device__ float g_num[NN * HID];
__device__ float g_out[NN * HID];

__device__ bf g_xh[NNP * HID],   g_xl[NNP * HID];
__device__ bf g_outh[NNP * HID], g_outl[NNP * HID];
__device__ bf g_h1h[NNP * HID],  g_h1l[NNP * HID];
__device__ bf g_eah[EEP * 32],   g_eal[EEP * 32];
__device__ bf g_w4h[256 * 1024], g_w4l[256 * 1024];   // [K=256][Wq|Wk|Wv|Wskip]
__device__ bf g_w1h[256 * 256],  g_w1l[256 * 256];
__device__ bf g_w2h[256 * 256],  g_w2l[256 * 256];
__device__ bf g_weh[32 * 256],   g_wel[32 * 256];
__device__ float g_b4[1024];

// ===================== scalar helpers =======================================
__device__ __forceinline__ float gelu_tanh(float x) {
    float x3 = x * x * x;
    float t = tanhf(0.7978845608028654f * (x + 0.044715f * x3));
    return 0.5f * x * (1.0f + t);
}
__device__ __forceinline__ void atomicMaxF(float* addr, float val) {
    if (val >= 0.0f) atomicMax(reinterpret_cast<int*>(addr), __float_as_int(val));
    else             atomicMin(reinterpret_cast<unsigned int*>(addr), __float_as_uint(val));
}
__device__ __forceinline__ void split2(float v, bf& h, bf& l) {
    h = __float2bfloat16(v);
    l = __float2bfloat16(v - __bfloat162float(h));
}

// ===================== conversion kernels ===================================
__global__ void cvt_split(const float* __restrict__ src, bf* __restrict__ h,
                          bf* __restrict__ l, int n) {
    int i = blockIdx.x * blockDim.x + threadIdx.x;
    if (i >= n) return;
    split2(src[i], h[i], l[i]);
}

#define W4_SZ   (256 * 1024)
#define W1_OFF  W4_SZ
#define W2_OFF  (W1_OFF + 65536)
#define WE_OFF  (W2_OFF + 65536)
#define B4_OFF  (WE_OFF + 8192)
#define CW_TOT  (B4_OFF + 1024)

__global__ void cvt_weights(const float* __restrict__ Wq, const float* __restrict__ Wk,
                            const float* __restrict__ Wv, const float* __restrict__ Ws,
                            const float* __restrict__ W1, const float* __restrict__ W2,
                            const float* __restrict__ We, const float* __restrict__ bq,
                            const float* __restrict__ bk, const float* __restrict__ bv) {
    int i = blockIdx.x * blockDim.x + threadIdx.x;
    if (i < W4_SZ) {
        int k = i >> 10, j = i & 1023, g = j >> 8, n = j & 255;
        const float* W = (g == 0) ? Wq : (g == 1) ? Wk : (g == 2) ? Wv : Ws;
        split2(W[k * 256 + n], g_w4h[i], g_w4l[i]);
    } else if (i < W2_OFF) {
        int t = i - W1_OFF; split2(W1[t], g_w1h[t], g_w1l[t]);
    } else if (i < WE_OFF) {
        int t = i - W2_OFF; split2(W2[t], g_w2h[t], g_w2l[t]);
    } else if (i < B4_OFF) {
        int t = i - WE_OFF; split2(We[t], g_weh[t], g_wel[t]);
    } else if (i < CW_TOT) {
        int t = i - B4_OFF, g = t >> 8, n = t & 255;
        g_b4[t] = (g == 0) ? bq[n] : (g == 1) ? bk[n] : (g == 2) ? bv[n] : 0.0f;
    }
}

// ===================== pipelined wmma GEMM ==================================
// C[M, NTOT] = (Ah+Al)[M,KF] @ (Bh+Bl)[KF,NTOT], 3-term bf16 split, fp32 acc.
// CTA tile 128x128; 8 warps (4m x 2n), warp tile 32x64 (2x4 frags).
// blockIdx.x = n-block (fast -> A reuse via L2), blockIdx.y = m-block.
// EPI: 0 f32 | 1 +bias f32 | 2 +bias,gelu -> bf16 hi/lo | 3 +bias,gelu,+res -> f32
static constexpr int APITCH = 72, BPITCH = 136;
static constexpr int ABYTES = 128 * APITCH * 2;   // 18432
static constexpr int BBYTES = 64 * BPITCH * 2;    // 17408

__device__ __forceinline__ void prefetch_tiles(
    uint32_t sbase, int Bbase,
    const bf* __restrict__ Ah, const bf* __restrict__ Al,
    const bf* __restrict__ Bh, const bf* __restrict__ Bl,
    int NTOT, int KF, int CHUNK, int row0, int n0, int c, int buf, int tid)
{
    const int CB = CHUNK / 8;
    const bf* Ag[2] = {Ah, Al};
    const bf* Bg[2] = {Bh, Bl};
#pragma unroll
    for (int hl = 0; hl < 2; hl++) {
        uint32_t sA = sbase + (uint32_t)(buf * 2 + hl) * ABYTES;
        const bf* srcA = Ag[hl] + (size_t)row0 * KF + c * CHUNK;
        for (int i = tid; i < 128 * CB; i += 256) {
            int r = i / CB, cc = i - r * CB;
            CP_ASYNC16(sA + r * (APITCH * 2) + cc * 16, srcA + (size_t)r * KF + cc * 8);
        }
        uint32_t sB = sbase + Bbase + (uint32_t)(buf * 2 + hl) * BBYTES;
        const bf* srcB = Bg[hl] + (size_t)(c * CHUNK) * NTOT + n0;
        for (int i = tid; i < CHUNK * 16; i += 256) {
            int r = i >> 4, cc = i & 15;
            CP_ASYNC16(sB + r * (BPITCH * 2) + cc * 16, srcB + (size_t)r * NTOT + cc * 8);
        }
    }
}

template <int KF, int EPI>
__global__ void __launch_bounds__(256) wgemm(
    const bf* __restrict__ Ah, const bf* __restrict__ Al,
    const bf* __restrict__ Bh, const bf* __restrict__ Bl, int NTOT,
    const float* __restrict__ bias, const float* __restrict__ res,
    float* __restrict__ O0, float* __restrict__ O1,
    float* __restrict__ O2, float* __restrict__ O3,
    bf* __restrict__ Ch, bf* __restrict__ Cl, int M)
{
    constexpr int CHUNK = (KF < 64) ? KF : 64;
    constexpr int NCH = KF / CHUNK;
    constexpr int NBUF = (NCH > 1) ? 2 : 1;
    constexpr int BBASE = NBUF * 2 * ABYTES;

    extern __shared__ char smem[];
    const uint32_t sbase = smem_u32(smem);

    int tid = threadIdx.x;
    int wid = tid >> 5;
    int mw = wid >> 1, nw = wid & 1;
    int n0 = blockIdx.x * 128;
    int row0 = blockIdx.y * 128;

    wmma::fragment<wmma::accumulator, 16, 16, 16, float> acc[2][4];
#pragma unroll
    for (int i = 0; i < 2; i++)
#pragma unroll
        for (int j = 0; j < 4; j++) wmma::fill_fragment(acc[i][j], 0.0f);

    prefetch_tiles(sbase, BBASE, Ah, Al, Bh, Bl, NTOT, KF, CHUNK, row0, n0, 0, 0, tid);
    CP_COMMIT();

#pragma unroll 1
    for (int c = 0; c < NCH; c++) {
        if (c + 1 < NCH) {
            prefetch_tiles(sbase, BBASE, Ah, Al, Bh, Bl, NTOT, KF, CHUNK, row0, n0,
                           c + 1, (c + 1) & 1, tid);
            CP_COMMIT();
            CP_WAIT(1);
        } else {
            CP_WAIT(0);
        }
        __syncthreads();

        int buf = (NBUF > 1) ? (c & 1) : 0;
        const bf* sAh = reinterpret_cast<const bf*>(smem + (size_t)(buf * 2 + 0) * ABYTES);
        const bf* sAl = reinterpret_cast<const bf*>(smem + (size_t)(buf * 2 + 1) * ABYTES);
        const bf* sBh = reinterpret_cast<const bf*>(smem + BBASE + (size_t)(buf * 2 + 0) * BBYTES);
        const bf* sBl = reinterpret_cast<const bf*>(smem + BBASE + (size_t)(buf * 2 + 1) * BBYTES);

#pragma unroll
        for (int ks = 0; ks < CHUNK / 16; ks++) {
            wmma::fragment<wmma::matrix_a, 16, 16, 16, bf, wmma::row_major> fah[2], fal[2];
            wmma::load_matrix_sync(fah[0], sAh + (mw * 32) * APITCH + ks * 16, APITCH);
            wmma::load_matrix_sync(fah[1], sAh + (mw * 32 + 16) * APITCH + ks * 16, APITCH);
            wmma::load_matrix_sync(fal[0], sAl + (mw * 32) * APITCH + ks * 16, APITCH);
            wmma::load_matrix_sync(fal[1], sAl + (mw * 32 + 16) * APITCH + ks * 16, APITCH);
#pragma unroll
            for (int j = 0; j < 4; j++) {
                wmma::fragment<wmma::matrix_b, 16, 16, 16, bf, wmma::row_major> fbh, fbl;
                wmma::load_matrix_sync(fbh, sBh + (ks * 16) * BPITCH + nw * 64 + j * 16, BPITCH);
                wmma::load_matrix_sync(fbl, sBl + (ks * 16) * BPITCH + nw * 64 + j * 16, BPITCH);
#pragma unroll
                for (int i = 0; i < 2; i++) {
                    wmma::mma_sync(acc[i][j], fah[i], fbh, acc[i][j]);
                    wmma::mma_sync(acc[i][j], fah[i], fbl, acc[i][j]);
                    wmma::mma_sync(acc[i][j], fal[i], fbh, acc[i][j]);
                }
            }
        }
        __syncthreads();
    }

    // ---- epilogue: frags -> smem stage -> coalesced guarded stores ----
    float* stage = reinterpret_cast<float*>(smem);   // [128][132]
    {
        int base = (mw * 32) * 132 + nw * 64;
#pragma unroll
        for (int i = 0; i < 2; i++)
#pragma unroll
            for (int j = 0; j < 4; j++)
                wmma::store_matrix_sync(stage + base + i * 16 * 132 + j * 16,
                                        acc[i][j], 132, wmma::mem_row_major);
    }
    __syncthreads();

    float* Of = O0;
    if (EPI != 2) {
        int which = n0 >> 8;
        Of = (which == 0) ? O0 : (which == 1) ? O1 : (which == 2) ? O2 : O3;
    }
    int cb0 = n0 & 255;

    for (int i = tid; i < 128 * 32; i += 256) {
        int r = i >> 5, c4 = i & 31;
        int grow = row0 + r;
        if (grow >= M) continue;
        float4 v = *reinterpret_cast<float4*>(stage + r * 132 + c4 * 4);
        if (EPI >= 1) {
            const float* bp = bias + n0 + c4 * 4;
            v.x += bp[0]; v.y += bp[1]; v.z += bp[2]; v.w += bp[3];
        }
        if (EPI >= 2) {
            v.x = gelu_tanh(v.x); v.y = gelu_tanh(v.y);
            v.z = gelu_tanh(v.z); v.w = gelu_tanh(v.w);
        }
        size_t idx = (size_t)grow * 256 + cb0 + c4 * 4;
        if (EPI == 2) {
            bf h0, l0, h1, l1, h2, l2, h3, l3;
            split2(v.x, h0, l0); split2(v.y, h1, l1);
            split2(v.z, h2, l2); split2(v.w, h3, l3);
            __nv_bfloat162 hh0{h0, h1}, hh1{h2, h3}, ll0{l0, l1}, ll1{l2, l3};
            *reinterpret_cast<__nv_bfloat162*>(Ch + idx)     = hh0;
            *reinterpret_cast<__nv_bfloat162*>(Ch + idx + 2) = hh1;
            *reinterpret_cast<__nv_bfloat162*>(Cl + idx)     = ll0;
            *reinterpret_cast<__nv_bfloat162*>(Cl + idx + 2) = ll1;
        } else {
            if (EPI == 3) {
                float4 rr = *reinterpret_cast<const float4*>(res + idx);
                v.x += rr.x; v.y += rr.y; v.z += rr.z; v.w += rr.w;
            }
            *reinterpret_cast<float4*>(Of + idx) = v;
        }
    }
}

// ===================== attention kernels ====================================
__global__ void init_kernel() {
    int i = blockIdx.x * blockDim.x + threadIdx.x;
    if (i < NN * HH) { g_m[i] = -INFINITY; g_denom[i] = 0.0f; }
    if (i < NN * HID) g_num[i] = 0.0f;
}

__global__ void edge_logits_kernel(const int* __restrict__ ei) {
    int warp = (blockIdx.x * blockDim.x + threadIdx.x) >> 5;
    int lane = threadIdx.x & 31;
    if (warp >= EE) return;
    int src = ei[warp];
    int dst = ei[EE + warp];
    const float* qrow = g_q + (size_t)dst * 256;
    const float* krow = g_k + (size_t)src * 256;
    const float* erow = g_e + (size_t)warp * 256;
    float s[8];
#pragma unroll
    for (int h = 0; h < 8; h++) {
        int j = h * 32 + lane;
        s[h] = qrow[j] * (krow[j] + erow[j]);
    }
#pragma unroll
    for (int off = 16; off; off >>= 1)
#pragma unroll
        for (int h = 0; h < 8; h++) s[h] += __shfl_xor_sync(0xffffffffu, s[h], off);
    if (lane < 8) {
        float lg = s[lane] * 0.17677669529663687f;
        g_logits[(size_t)warp * 8 + lane] = lg;
        atomicMaxF(&g_m[dst * 8 + lane], lg);
    }
}

__global__ void edge_accum_kernel(const int* __restrict__ ei) {
    int warp = (blockIdx.x * blockDim.x + threadIdx.x) >> 5;
    int lane = threadIdx.x & 31;
    if (warp >= EE) return;
    int src = ei[warp];
    int dst = ei[EE + warp];
    float a = 0.0f;
    if (lane < 8) {
        a = expf(g_logits[(size_t)warp * 8 + lane] - g_m[dst * 8 + lane]);
        atomicAdd(&g_denom[dst * 8 + lane], a);
    }
    float ah[8];
#pragma unroll
    for (int h = 0; h < 8; h++) ah[h] = __shfl_sync(0xffffffffu, a, h);

    const float4* v4 = reinterpret_cast<const float4*>(g_v + (size_t)src * 256);
    const float4* e4 = reinterpret_cast<const float4*>(g_e + (size_t)warp * 256);
    float* nrow = g_num + (size_t)dst * 256;
#pragma unroll
    for (int half = 0; half < 2; half++) {
        int col4 = half * 32 + lane;
        float al = ah[col4 >> 3];
        float4 vv = v4[col4];
        float4 ee = e4[col4];
        redAdd4(nrow + col4 * 4,
                (vv.x + ee.x) * al, (vv.y + ee.y) * al,
                (vv.z + ee.z) * al, (vv.w + ee.w) * al);
    }
}

__global__ void node_out_kernel() {
    int i = blockIdx.x * blockDim.x + threadIdx.x;
    if (i >= NN * HID) return;
    int n = i >> 8;
    int h = (i & 255) >> 5;
    float o = g_num[i] / (g_denom[n * 8 + h] + 1e-16f) + g_skip[i];
    g_out[i] = o;
    split2(o, g_outh[i], g_outl[i]);
}

// ===================== launch ===============================================
extern "C" void kernel_launch(void* const* d_in, const int* in_sizes, int n_in,
                              void* d_out, int out_size) {
    const float* x         = (const float*)d_in[0];
    const int*   edge_idx  = (const int*)d_in[1];
    const float* edge_attr = (const float*)d_in[2];
    const float* Wq = (const float*)d_in[3];
    const float* bq = (const float*)d_in[4];
    const float* Wk = (const float*)d_in[5];
    const float* bk = (const float*)d_in[6];
    const float* Wv = (const float*)d_in[7];
    const float* bv = (const float*)d_in[8];
    const float* We = (const float*)d_in[9];
    const float* Wskip = (const float*)d_in[10];
    const float* W1 = (const float*)d_in[11];
    const float* b1 = (const float*)d_in[12];
    const float* W2 = (const float*)d_in[13];
    const float* b2 = (const float*)d_in[14];

    void *pq, *pk, *pv, *pskip, *pe, *pout;
    void *pxh, *pxl, *pouth, *poutl, *ph1h, *ph1l, *peah, *peal;
    void *pw4h, *pw4l, *pw1h, *pw1l, *pw2h, *pw2l, *pweh, *pwel, *pb4;
    cudaGetSymbolAddress(&pq, g_q);       cudaGetSymbolAddress(&pk, g_k);
    cudaGetSymbolAddress(&pv, g_v);       cudaGetSymbolAddress(&pskip, g_skip);
    cudaGetSymbolAddress(&pe, g_e);       cudaGetSymbolAddress(&pout, g_out);
    cudaGetSymbolAddress(&pxh, g_xh);     cudaGetSymbolAddress(&pxl, g_xl);
    cudaGetSymbolAddress(&pouth, g_outh); cudaGetSymbolAddress(&poutl, g_outl);
    cudaGetSymbolAddress(&ph1h, g_h1h);   cudaGetSymbolAddress(&ph1l, g_h1l);
    cudaGetSymbolAddress(&peah, g_eah);   cudaGetSymbolAddress(&peal, g_eal);
    cudaGetSymbolAddress(&pw4h, g_w4h);   cudaGetSymbolAddress(&pw4l, g_w4l);
    cudaGetSymbolAddress(&pw1h, g_w1h);   cudaGetSymbolAddress(&pw1l, g_w1l);
    cudaGetSymbolAddress(&pw2h, g_w2h);   cudaGetSymbolAddress(&pw2l, g_w2l);
    cudaGetSymbolAddress(&pweh, g_weh);   cudaGetSymbolAddress(&pwel, g_wel);
    cudaGetSymbolAddress(&pb4, g_b4);

    const int SMEM_BIG  = 2 * 2 * (ABYTES + BBYTES);  // 143360
    const int SMEM_EDGE = 2 * (ABYTES + BBYTES);      // 71680
    cudaFuncSetAttribute(wgemm<256,1>, cudaFuncAttributeMaxDynamicSharedMemorySize, SMEM_BIG);
    cudaFuncSetAttribute(wgemm<256,2>, cudaFuncAttributeMaxDynamicSharedMemorySize, SMEM_BIG);
    cudaFuncSetAttribute(wgemm<256,3>, cudaFuncAttributeMaxDynamicSharedMemorySize, SMEM_BIG);
    cudaFuncSetAttribute(wgemm<32,0>,  cudaFuncAttributeMaxDynamicSharedMemorySize, SMEM_EDGE);

    // launch order tuned so ncu (-s 5) captures the fused QKVS GEMM
    init_kernel<<<(NN * HID + 255) / 256, 256>>>();                               // 0
    cvt_weights<<<(CW_TOT + 255) / 256, 256>>>(Wq, Wk, Wv, Wskip, W1, W2, We,
                                               bq, bk, bv);                       // 1
    cvt_split<<<(NN * HID + 255) / 256, 256>>>(x, (bf*)pxh, (bf*)pxl, NN * HID);  // 2
    cvt_split<<<(EE * 32 + 255) / 256, 256>>>(edge_attr, (bf*)peah, (bf*)peal,
                                              EE * 32);                           // 3

    // 4: edge projection e = edge_attr @ We   [EEP x 32] @ [32 x 256]
    wgemm<32,0><<<dim3(2, EEP / 128), 256, SMEM_EDGE>>>(
        (bf*)peah, (bf*)peal, (bf*)pweh, (bf*)pwel, 256,
        nullptr, nullptr, (float*)pe, nullptr, nullptr, nullptr, nullptr, nullptr, EE);

    // 5: fused QKVS  [NNP x 256] @ [256 x 1024]
    wgemm<256,1><<<dim3(8, NNP / 128), 256, SMEM_BIG>>>(
        (bf*)pxh, (bf*)pxl, (bf*)pw4h, (bf*)pw4l, 1024,
        (const float*)pb4, nullptr,
        (float*)pq, (float*)pk, (float*)pv, (float*)pskip, nullptr, nullptr, NN);

    // attention
    int edgeBlocks = (EE + 7) / 8;
    edge_logits_kernel<<<edgeBlocks, 256>>>(edge_idx);                            // 6
    edge_accum_kernel<<<edgeBlocks, 256>>>(edge_idx);                             // 7
    node_out_kernel<<<(NN * HID + 255) / 256, 256>>>();                           // 8

    // MLP
    wgemm<256,2><<<dim3(2, NNP / 128), 256, SMEM_BIG>>>(
        (bf*)pouth, (bf*)poutl, (bf*)pw1h, (bf*)pw1l, 256,
        b1, nullptr, nullptr, nullptr, nullptr, nullptr,
        (bf*)ph1h, (bf*)ph1l, NN);                                                // 9
    wgemm<256,3><<<dim3(2, NNP / 128), 256, SMEM_BIG>>>(
        (bf*)ph1h, (bf*)ph1l, (bf*)pw2h, (bf*)pw2l, 256,
        b2, (const float*)pout, (float*)d_out, nullptr, nullptr, nullptr,
        nullptr, nullptr, NN);                                                    // 10
}